// round 15
// baseline (speedup 1.0000x reference)
#include <cuda_runtime.h>
#include <cuda_fp16.h>
#include <cstdint>

#define B_N 2048
#define H_N 4096
#define E_N 8
#define L_N 512

// ---------------- scratch ----------------
__device__ int   g_counts[E_N];
__device__ int   g_rows[E_N][B_N];
__device__ float g_pen[25];
__device__ int   g_ntiles;
__device__ int   g_tile_ctr;
__device__ uint32_t g_tiles[512];

__device__ __align__(256) __half g_hid_h[B_N * H_N];
__device__ __align__(256) __half g_W_h[E_N * L_N * H_N];

__global__ void init_kernel() {
    int t = threadIdx.x;
    if (t < E_N) g_counts[t] = 0;
    if (t < 25)  g_pen[t]    = 0.0f;
    if (t == 0)  g_tile_ctr  = 0;
}

// ---------------- expert selection ----------------
__global__ void select_kernel(const float* __restrict__ envs,
                              const int* __restrict__ idx32,
                              const float* __restrict__ gumbel) {
    int b = blockIdx.x * blockDim.x + threadIdx.x;
    if (b >= B_N) return;
    int stride = (idx32[1] == 0) ? 2 : 1;   // int64-on-disk detection (idx = arange)
    int r = idx32[(size_t)b * stride];
    if (r < 0) r = 0;
    if (r >= B_N) r = B_N - 1;
    const float* ev = envs   + (size_t)r * E_N;
    const float* gv = gumbel + (size_t)b * E_N;
    float best = ev[0] + gv[0];
    int be = 0;
#pragma unroll
    for (int e = 1; e < E_N; e++) {
        float v = ev[e] + gv[e];
        if (v > best) { best = v; be = e; }
    }
    int pos = atomicAdd(&g_counts[be], 1);
    g_rows[be][pos] = b;
}

// ---------------- balanced tile list ----------------
// tile = (expert, 64-row m-chunk, 128-col l-block); enc = e<<12 | m<<4 | l
__global__ void build_tiles_kernel() {
    if (threadIdx.x == 0) {
        int n = 0;
        for (int e = 0; e < E_N; e++) {
            int mc = (g_counts[e] + 63) >> 6;
            for (int m = 0; m < mc; m++)
                for (int l = 0; l < 4; l++)
                    g_tiles[n++] = (e << 12) | (m << 4) | l;
        }
        g_ntiles = n;
    }
}

// -------- fused converter: W -> fp16 and hidden -> fp16 (pure streaming) -------
#define CVT_GRID 1184

__global__ void __launch_bounds__(256)
convert_kernel(const float* __restrict__ W, const float* __restrict__ hidden) {
    const int WN4 = E_N * L_N * H_N / 4;   // 4194304
    const int HN4 = B_N * H_N / 4;         // 2097152
    const int stride = CVT_GRID * 256;
    int t0 = blockIdx.x * 256 + threadIdx.x;

    const float4* Wv = (const float4*)W;
    uint2* wh = (uint2*)g_W_h;
    for (int i = t0; i < WN4; i += stride) {
        float4 v = Wv[i];
        __half2 h01 = __floats2half2_rn(v.x, v.y);
        __half2 h23 = __floats2half2_rn(v.z, v.w);
        uint2 p;
        p.x = *reinterpret_cast<uint32_t*>(&h01);
        p.y = *reinterpret_cast<uint32_t*>(&h23);
        wh[i] = p;
    }
    const float4* hv = (const float4*)hidden;
    uint2* hh = (uint2*)g_hid_h;
    for (int i = t0; i < HN4; i += stride) {
        float4 v = hv[i];
        __half2 h01 = __floats2half2_rn(v.x, v.y);
        __half2 h23 = __floats2half2_rn(v.z, v.w);
        uint2 p;
        p.x = *reinterpret_cast<uint32_t*>(&h01);
        p.y = *reinterpret_cast<uint32_t*>(&h23);
        hh[i] = p;
    }
}

__global__ void finalize_kernel(float* __restrict__ pen_out) {
    if (threadIdx.x == 0) {
        float acc = 0.f;
        float ss = g_pen[24];
#pragma unroll
        for (int e = 0; e < 8; e++) {
            float diff = g_pen[e] - 0.25f * g_pen[8 + e] + ss * (1.0f / 64.0f);
            float l1 = g_pen[16 + e];
            acc += diff / (l1 * l1);
        }
        pen_out[0] = acc * 0.125f;
    }
}

// stats over one group of 8 expert values (4 components of float4)
static __device__ __forceinline__ void stats8(const float4* w, float* q, float* c,
                                              float* l1, float& ss) {
#pragma unroll
    for (int comp = 0; comp < 4; comp++) {
        float we[8];
#pragma unroll
        for (int e = 0; e < 8; e++) {
            float4 t = w[e];
            we[e] = (comp == 0) ? t.x : (comp == 1) ? t.y : (comp == 2) ? t.z : t.w;
        }
        float s = 0.f;
#pragma unroll
        for (int e = 0; e < 8; e++) s += we[e];
        ss = fmaf(s, s, ss);
#pragma unroll
        for (int e = 0; e < 8; e++) {
            q[e]  = fmaf(we[e], we[e], q[e]);
            c[e]  = fmaf(we[e], s,     c[e]);
            l1[e] += fabsf(we[e]);
        }
    }
}

// ====== persistent fp16 GEMM + hidden penalty-stats warp (1 CTA/SM) ======
// 288 threads: warps 0-7 = GEMM (64x128x128 tile, named barrier 1 x 256),
// warp 8 = penalty stats over fp32 W (DRAM-idle window under the GEMM).

#define TMB 64
#define TNB 128
#define TK 128
#define NSTAGE 3
#define STG_B 49152
#define NIT (H_N / TK)          // 32
#define SMEM_DYN (NSTAGE * STG_B + 1024)
#define GRID_GEMM 148

static __device__ __forceinline__ uint32_t s2u(const void* p) {
    return (uint32_t)__cvta_generic_to_shared(p);
}
static __device__ __forceinline__ void cp16(uint32_t s, const __half* g, bool pred) {
    int sz = pred ? 16 : 0;
    asm volatile("cp.async.cg.shared.global [%0], [%1], 16, %2;"
                 :: "r"(s), "l"(g), "r"(sz));
}
#define GBAR() asm volatile("bar.sync 1, 256;" ::: "memory")

#define LDSM4(r0, r1, r2, r3, a) \
    asm volatile("ldmatrix.sync.aligned.m8n8.x4.shared.b16 {%0,%1,%2,%3}, [%4];" \
                 : "=r"(r0), "=r"(r1), "=r"(r2), "=r"(r3) : "r"(a))

#define MMAF16(d, A, b0, b1) \
    asm volatile("mma.sync.aligned.m16n8k16.row.col.f32.f16.f16.f32 " \
                 "{%0,%1,%2,%3}, {%4,%5,%6,%7}, {%8,%9}, {%0,%1,%2,%3};" \
                 : "+f"((d)[0]), "+f"((d)[1]), "+f"((d)[2]), "+f"((d)[3]) \
                 : "r"((A)[0]), "r"((A)[1]), "r"((A)[2]), "r"((A)[3]), \
                   "r"(b0), "r"(b1))

#define LOAD_FRAG(BUF, S4) do {                                              \
    uint32_t _AS = base + ((S4) >> 2) * 8192;                                \
    uint32_t _BS = base + 16384 + ((S4) >> 2) * 16384;                       \
    int _s4l = (S4) & 3;                                                     \
    _Pragma("unroll")                                                        \
    for (int _mt = 0; _mt < 2; _mt++) {                                      \
        int _ch = (2 * _s4l + a_h) ^ axr[_mt];                               \
        LDSM4(af[BUF][_mt][0], af[BUF][_mt][1], af[BUF][_mt][2],             \
              af[BUF][_mt][3], _AS + (arow[_mt] + _ch * 8) * 2);             \
    }                                                                        \
    _Pragma("unroll")                                                        \
    for (int _p = 0; _p < 2; _p++) {                                         \
        int _ch = (2 * _s4l + b_h) ^ bxr[_p];                                \
        uint32_t _r0, _r1, _r2, _r3;                                         \
        LDSM4(_r0, _r1, _r2, _r3, _BS + (brow[_p] + _ch * 8) * 2);           \
        bf[BUF][2 * _p][0] = _r0;     bf[BUF][2 * _p][1] = _r1;              \
        bf[BUF][2 * _p + 1][0] = _r2; bf[BUF][2 * _p + 1][1] = _r3;          \
    }                                                                        \
} while (0)

extern __shared__ char dyn_raw[];

__global__ void __launch_bounds__(288, 1)
gemm_kernel(float* __restrict__ out, const float* __restrict__ Wfp32) {
    __shared__ int rowids[TMB];
    __shared__ int s_tile;

    int tid = threadIdx.x;
    int wid = tid >> 5, lane = tid & 31;

    if (wid == 8) {
        // ---- penalty stats warp: stream fp32 W, DRAM-bound, hidden under GEMM ----
        const int LH4 = (L_N * H_N) / 4;
        const float4* Wv = (const float4*)Wfp32;
        const int gs = GRID_GEMM * 32;
        float q[8], c[8], l1[8], ss = 0.0f;
#pragma unroll
        for (int e = 0; e < 8; e++) { q[e] = 0.f; c[e] = 0.f; l1[e] = 0.f; }

        for (int i0 = blockIdx.x * 32 + lane; i0 < LH4; i0 += 2 * gs) {
            float4 w0[8], w1[8];
            int i1 = i0 + gs;
            bool has2 = (i1 < LH4);
#pragma unroll
            for (int e = 0; e < 8; e++) w0[e] = Wv[(size_t)e * LH4 + i0];
            if (has2) {
#pragma unroll
                for (int e = 0; e < 8; e++) w1[e] = Wv[(size_t)e * LH4 + i1];
            }
            stats8(w0, q, c, l1, ss);
            if (has2) stats8(w1, q, c, l1, ss);
        }

        float vals[25];
#pragma unroll
        for (int e = 0; e < 8; e++) { vals[e] = q[e]; vals[8 + e] = c[e]; vals[16 + e] = l1[e]; }
        vals[24] = ss;
#pragma unroll
        for (int k = 0; k < 25; k++)
#pragma unroll
            for (int off = 16; off > 0; off >>= 1)
                vals[k] += __shfl_down_sync(0xFFFFFFFFu, vals[k], off);
        if (lane == 0)
#pragma unroll
            for (int k = 0; k < 25; k++) atomicAdd(&g_pen[k], vals[k]);
        return;
    }

    // ---- GEMM warps (0-7) ----
    uint32_t sbase = (s2u(dyn_raw) + 1023) & ~1023u;
    uint32_t stb[NSTAGE];
#pragma unroll
    for (int s = 0; s < NSTAGE; s++) stb[s] = sbase + s * STG_B;

    int lrow = tid >> 3;              // 0..31
    int lcc  = tid & 7;
    int lphys = lcc ^ (lrow & 7);
    int sOffA[2], sOffB[4];
#pragma unroll
    for (int i = 0; i < 2; i++) sOffA[i] = ((lrow + i * 32) * 64 + lphys * 8) * 2;
#pragma unroll
    for (int i = 0; i < 4; i++) sOffB[i] = ((lrow + i * 32) * 64 + lphys * 8) * 2;

    int wm = (wid & 1) * 32;
    int wn = (wid >> 1) * 32;
    int a_h = lane >> 4, a_r = lane & 15;
    int b_g = lane >> 3, b_sub = b_g >> 1, b_h = b_g & 1, b_r = lane & 7;

    int arow[2], axr[2];
#pragma unroll
    for (int mt = 0; mt < 2; mt++) {
        int r = wm + mt * 16 + a_r;
        arow[mt] = r * 64; axr[mt] = r & 7;
    }
    int brow[2], bxr[2];
#pragma unroll
    for (int p = 0; p < 2; p++) {
        int r = wn + p * 16 + b_sub * 8 + b_r;
        brow[p] = r * 64; bxr[p] = r & 7;
    }
    int gid = lane >> 2, tig = lane & 3;

    for (;;) {
        GBAR();   // previous tile fully done
        if (tid == 0) s_tile = atomicAdd(&g_tile_ctr, 1);
        GBAR();
        int t = s_tile;
        if (t >= g_ntiles) break;

        uint32_t enc = g_tiles[t];
        int e = enc >> 12;
        int mch = (enc >> 4) & 255;
        int l_base = (enc & 15) * TNB;
        int cnt = g_counts[e];

        if (tid < TMB) {
            int i = mch * TMB + tid;
            rowids[tid] = (i < cnt) ? g_rows[e][i] : -1;
        }
        GBAR();

        const __half* gA[2];
        const __half* gB[4];
        bool apred[2];
#pragma unroll
        for (int i = 0; i < 2; i++) {
            int row = lrow + i * 32;
            int g = rowids[row];
            apred[i] = (g >= 0);
            gA[i] = g_hid_h + (size_t)(apred[i] ? g : 0) * H_N + lcc * 8;
        }
#pragma unroll
        for (int i = 0; i < 4; i++) {
            int row = lrow + i * 32;
            gB[i] = g_W_h + ((size_t)e * L_N + l_base + row) * H_N + lcc * 8;
        }

        float acc[2][4][4];
#pragma unroll
        for (int mt = 0; mt < 2; mt++)
#pragma unroll
            for (int nt = 0; nt < 4; nt++)
#pragma unroll
                for (int j = 0; j < 4; j++) acc[mt][nt][j] = 0.f;

        // preload stages 0,1 (each stage = 2 k-blocks of 64)
#pragma unroll
        for (int p = 0; p < NSTAGE - 1; p++) {
            uint32_t b = stb[p];
            int koff = p * TK;
#pragma unroll
            for (int kb = 0; kb < 2; kb++) {
                int ko = koff + kb * 64;
#pragma unroll
                for (int i = 0; i < 2; i++)
                    cp16(b + kb * 8192 + sOffA[i], gA[i] + ko, apred[i]);
#pragma unroll
                for (int i = 0; i < 4; i++)
                    cp16(b + 16384 + kb * 16384 + sOffB[i], gB[i] + ko, true);
            }
            asm volatile("cp.async.commit_group;");
        }

        int cur = 0, nxt = NSTAGE - 1;
        for (int it = 0; it < NIT; it++) {
            asm volatile("cp.async.wait_group 1;");
            GBAR();

            int nc = it + NSTAGE - 1;
            if (nc < NIT) {
                uint32_t b = stb[nxt];
                int koff = nc * TK;
#pragma unroll
                for (int kb = 0; kb < 2; kb++) {
                    int ko = koff + kb * 64;
#pragma unroll
                    for (int i = 0; i < 2; i++)
                        cp16(b + kb * 8192 + sOffA[i], gA[i] + ko, apred[i]);
#pragma unroll
                    for (int i = 0; i < 4; i++)
                        cp16(b + 16384 + kb * 16384 + sOffB[i], gB[i] + ko, true);
                }
            }
            asm volatile("cp.async.commit_group;");

            uint32_t base = stb[cur];
            uint32_t af[2][2][4], bf[2][4][2];

            LOAD_FRAG(0, 0);
#pragma unroll
            for (int s4 = 0; s4 < 8; s4++) {
                int cb = s4 & 1, nb = cb ^ 1;
                if (s4 < 7) LOAD_FRAG(nb, s4 + 1);
#pragma unroll
                for (int mt = 0; mt < 2; mt++)
#pragma unroll
                    for (int nt = 0; nt < 4; nt++)
                        MMAF16(acc[mt][nt], af[cb][mt], bf[cb][nt][0], bf[cb][nt][1]);
            }
            cur = (cur + 1 == NSTAGE) ? 0 : cur + 1;
            nxt = (nxt + 1 == NSTAGE) ? 0 : nxt + 1;
        }

        // ---- epilogue ----
#pragma unroll
        for (int mt = 0; mt < 2; mt++) {
            int r0 = wm + mt * 16 + gid;
            int r1 = r0 + 8;
            int g0 = rowids[r0];
            int g1 = rowids[r1];
#pragma unroll
            for (int nt = 0; nt < 4; nt++) {
                int col = l_base + wn + nt * 8 + tig * 2;
                if (g0 >= 0)
                    *(float2*)(out + (size_t)g0 * L_N + col) =
                        make_float2(acc[mt][nt][0], acc[mt][nt][1]);
                if (g1 >= 0)
                    *(float2*)(out + (size_t)g1 * L_N + col) =
                        make_float2(acc[mt][nt][2], acc[mt][nt][3]);
            }
        }
    }
}

// ---------------- launch ----------------
extern "C" void kernel_launch(void* const* d_in, const int* in_sizes, int n_in,
                              void* d_out, int out_size) {
    const float* hidden = (const float*)d_in[0];
    const float* envs   = (const float*)d_in[1];
    const int*   idx32  = (const int*)d_in[2];
    const float* gumbel = (const float*)d_in[3];
    const float* W      = (const float*)d_in[4];
    float* out = (float*)d_out;

    cudaFuncSetAttribute(gemm_kernel,
                         cudaFuncAttributeMaxDynamicSharedMemorySize, SMEM_DYN);

    init_kernel<<<1, 32>>>();
    select_kernel<<<(B_N + 255) / 256, 256>>>(envs, idx32, gumbel);
    build_tiles_kernel<<<1, 32>>>();
    convert_kernel<<<CVT_GRID, 256>>>(W, hidden);

    gemm_kernel<<<GRID_GEMM, 288, SMEM_DYN>>>(out, W);

    if (out_size > B_N * L_N)
        finalize_kernel<<<1, 32>>>(out + (size_t)B_N * L_N);
}

// round 16
// speedup vs baseline: 1.1009x; 1.1009x over previous
#include <cuda_runtime.h>
#include <cuda_fp16.h>
#include <cstdint>

#define B_N 2048
#define H_N 4096
#define E_N 8
#define L_N 512

// ---------------- scratch ----------------
__device__ int   g_counts[E_N];
__device__ int   g_rows[E_N][B_N];
__device__ float g_pen[25];
__device__ int   g_ntiles;
__device__ int   g_tile_ctr;
__device__ int   g_sel_done;
__device__ uint32_t g_tiles[512];

__device__ __align__(256) __half g_hid_h[B_N * H_N];
__device__ __align__(256) __half g_W_h[E_N * L_N * H_N];

// -------- fused converter: W -> fp16, hidden -> fp16, + init (block 0) -------
#define CVT_GRID 1184

__global__ void __launch_bounds__(256)
convert_kernel(const float* __restrict__ W, const float* __restrict__ hidden) {
    if (blockIdx.x == 0 && threadIdx.x < 32) {
        int t = threadIdx.x;
        if (t < E_N) g_counts[t] = 0;
        if (t < 25)  g_pen[t]    = 0.0f;
        if (t == 0) { g_tile_ctr = 0; g_sel_done = 0; }
    }
    const int WN4 = E_N * L_N * H_N / 4;   // 4194304
    const int HN4 = B_N * H_N / 4;         // 2097152
    const int stride = CVT_GRID * 256;
    int t0 = blockIdx.x * 256 + threadIdx.x;

    const float4* Wv = (const float4*)W;
    uint2* wh = (uint2*)g_W_h;
    for (int i = t0; i < WN4; i += stride) {
        float4 v = Wv[i];
        __half2 h01 = __floats2half2_rn(v.x, v.y);
        __half2 h23 = __floats2half2_rn(v.z, v.w);
        uint2 p;
        p.x = *reinterpret_cast<uint32_t*>(&h01);
        p.y = *reinterpret_cast<uint32_t*>(&h23);
        wh[i] = p;
    }
    const float4* hv = (const float4*)hidden;
    uint2* hh = (uint2*)g_hid_h;
    for (int i = t0; i < HN4; i += stride) {
        float4 v = hv[i];
        __half2 h01 = __floats2half2_rn(v.x, v.y);
        __half2 h23 = __floats2half2_rn(v.z, v.w);
        uint2 p;
        p.x = *reinterpret_cast<uint32_t*>(&h01);
        p.y = *reinterpret_cast<uint32_t*>(&h23);
        hh[i] = p;
    }
}

// ---------------- expert selection + tile build (last-block ticket) ----------
__global__ void select_kernel(const float* __restrict__ envs,
                              const int* __restrict__ idx32,
                              const float* __restrict__ gumbel) {
    int b = blockIdx.x * blockDim.x + threadIdx.x;
    if (b < B_N) {
        int stride = (idx32[1] == 0) ? 2 : 1;   // int64-on-disk detection (idx = arange)
        int r = idx32[(size_t)b * stride];
        if (r < 0) r = 0;
        if (r >= B_N) r = B_N - 1;
        const float* ev = envs   + (size_t)r * E_N;
        const float* gv = gumbel + (size_t)b * E_N;
        float best = ev[0] + gv[0];
        int be = 0;
#pragma unroll
        for (int e = 1; e < E_N; e++) {
            float v = ev[e] + gv[e];
            if (v > best) { best = v; be = e; }
        }
        int pos = atomicAdd(&g_counts[be], 1);
        g_rows[be][pos] = b;
    }
    __syncthreads();
    if (threadIdx.x == 0) {
        __threadfence();
        int tk = atomicAdd(&g_sel_done, 1);
        if (tk == (int)gridDim.x - 1) {
            // all selection atomics visible; build balanced tile list
            int n = 0;
            for (int e = 0; e < E_N; e++) {
                int mc = (g_counts[e] + 63) >> 6;
                for (int m = 0; m < mc; m++)
                    for (int l = 0; l < 4; l++)
                        g_tiles[n++] = (e << 12) | (m << 4) | l;
            }
            g_ntiles = n;
        }
    }
}

// ------- penalty stats from fp16 W copy (33MB read; zero-mean fp16 rounding) ----
#define ST_GRID 1024
#define ST_BLK  128

__global__ void __launch_bounds__(ST_BLK, 4)
stats_kernel() {
    const int LH4 = (L_N * H_N) / 4;   // groups of 4 halves (uint2 loads)
    const uint2* Wv = (const uint2*)g_W_h;
    const int stride = ST_GRID * ST_BLK;
    const int iters = LH4 / stride;    // 4

    float q[8], c[8], l1[8], ss = 0.0f;
#pragma unroll
    for (int e = 0; e < 8; e++) { q[e] = 0.f; c[e] = 0.f; l1[e] = 0.f; }

    int i = blockIdx.x * ST_BLK + threadIdx.x;

    uint2 buf[8];
#pragma unroll
    for (int e = 0; e < 8; e++) buf[e] = Wv[(size_t)e * LH4 + i];

    for (int it = 0; it < iters; it++) {
        uint2 nxt[8];
        int i2 = i + stride;
        if (it + 1 < iters) {
#pragma unroll
            for (int e = 0; e < 8; e++) nxt[e] = Wv[(size_t)e * LH4 + i2];
        }
        float w[8][4];
#pragma unroll
        for (int e = 0; e < 8; e++) {
            __half2 p0 = *reinterpret_cast<__half2*>(&buf[e].x);
            __half2 p1 = *reinterpret_cast<__half2*>(&buf[e].y);
            float2 f0 = __half22float2(p0);
            float2 f1 = __half22float2(p1);
            w[e][0] = f0.x; w[e][1] = f0.y; w[e][2] = f1.x; w[e][3] = f1.y;
        }
#pragma unroll
        for (int comp = 0; comp < 4; comp++) {
            float s = 0.f;
#pragma unroll
            for (int e = 0; e < 8; e++) s += w[e][comp];
            ss = fmaf(s, s, ss);
#pragma unroll
            for (int e = 0; e < 8; e++) {
                float we = w[e][comp];
                q[e]  = fmaf(we, we, q[e]);
                c[e]  = fmaf(we, s,  c[e]);
                l1[e] += fabsf(we);
            }
        }
        if (it + 1 < iters) {
#pragma unroll
            for (int e = 0; e < 8; e++) buf[e] = nxt[e];
            i = i2;
        }
    }

    __shared__ float red[25][136];
    int tid = threadIdx.x;
#pragma unroll
    for (int e = 0; e < 8; e++) {
        red[e][tid]      = q[e];
        red[8 + e][tid]  = c[e];
        red[16 + e][tid] = l1[e];
    }
    red[24][tid] = ss;
    __syncthreads();
    if (tid < 25) {
        float s = 0.f;
#pragma unroll 8
        for (int j = 0; j < ST_BLK; j++) s += red[tid][j];
        atomicAdd(&g_pen[tid], s);
    }
}

__global__ void finalize_kernel(float* __restrict__ pen_out) {
    if (threadIdx.x == 0) {
        float acc = 0.f;
        float ss = g_pen[24];
#pragma unroll
        for (int e = 0; e < 8; e++) {
            float diff = g_pen[e] - 0.25f * g_pen[8 + e] + ss * (1.0f / 64.0f);
            float l1 = g_pen[16 + e];
            acc += diff / (l1 * l1);
        }
        pen_out[0] = acc * 0.125f;
    }
}

// ====== persistent fp16 tensor-core grouped GEMM (1 CTA/SM, TK=128) ======
// (R14 winner, unchanged)

#define TMB 64
#define TNB 128
#define TK 128
#define NSTAGE 3
#define STG_B 49152
#define NIT (H_N / TK)          // 32
#define SMEM_DYN (NSTAGE * STG_B + 1024)
#define GRID_GEMM 148

static __device__ __forceinline__ uint32_t s2u(const void* p) {
    return (uint32_t)__cvta_generic_to_shared(p);
}
static __device__ __forceinline__ void cp16(uint32_t s, const __half* g, bool pred) {
    int sz = pred ? 16 : 0;
    asm volatile("cp.async.cg.shared.global [%0], [%1], 16, %2;"
                 :: "r"(s), "l"(g), "r"(sz));
}

#define LDSM4(r0, r1, r2, r3, a) \
    asm volatile("ldmatrix.sync.aligned.m8n8.x4.shared.b16 {%0,%1,%2,%3}, [%4];" \
                 : "=r"(r0), "=r"(r1), "=r"(r2), "=r"(r3) : "r"(a))

#define MMAF16(d, A, b0, b1) \
    asm volatile("mma.sync.aligned.m16n8k16.row.col.f32.f16.f16.f32 " \
                 "{%0,%1,%2,%3}, {%4,%5,%6,%7}, {%8,%9}, {%0,%1,%2,%3};" \
                 : "+f"((d)[0]), "+f"((d)[1]), "+f"((d)[2]), "+f"((d)[3]) \
                 : "r"((A)[0]), "r"((A)[1]), "r"((A)[2]), "r"((A)[3]), \
                   "r"(b0), "r"(b1))

#define LOAD_FRAG(BUF, S4) do {                                              \
    uint32_t _AS = base + ((S4) >> 2) * 8192;                                \
    uint32_t _BS = base + 16384 + ((S4) >> 2) * 16384;                       \
    int _s4l = (S4) & 3;                                                     \
    _Pragma("unroll")                                                        \
    for (int _mt = 0; _mt < 2; _mt++) {                                      \
        int _ch = (2 * _s4l + a_h) ^ axr[_mt];                               \
        LDSM4(af[BUF][_mt][0], af[BUF][_mt][1], af[BUF][_mt][2],             \
              af[BUF][_mt][3], _AS + (arow[_mt] + _ch * 8) * 2);             \
    }                                                                        \
    _Pragma("unroll")                                                        \
    for (int _p = 0; _p < 2; _p++) {                                         \
        int _ch = (2 * _s4l + b_h) ^ bxr[_p];                                \
        uint32_t _r0, _r1, _r2, _r3;                                         \
        LDSM4(_r0, _r1, _r2, _r3, _BS + (brow[_p] + _ch * 8) * 2);           \
        bf[BUF][2 * _p][0] = _r0;     bf[BUF][2 * _p][1] = _r1;              \
        bf[BUF][2 * _p + 1][0] = _r2; bf[BUF][2 * _p + 1][1] = _r3;          \
    }                                                                        \
} while (0)

extern __shared__ char dyn_raw[];

__global__ void __launch_bounds__(256, 1)
gemm_kernel(float* __restrict__ out) {
    __shared__ int rowids[TMB];
    __shared__ int s_tile;

    int tid = threadIdx.x;
    int wid = tid >> 5, lane = tid & 31;

    uint32_t sbase = (s2u(dyn_raw) + 1023) & ~1023u;
    uint32_t stb[NSTAGE];
#pragma unroll
    for (int s = 0; s < NSTAGE; s++) stb[s] = sbase + s * STG_B;

    int lrow = tid >> 3;              // 0..31
    int lcc  = tid & 7;
    int lphys = lcc ^ (lrow & 7);
    int sOffA[2], sOffB[4];
#pragma unroll
    for (int i = 0; i < 2; i++) sOffA[i] = ((lrow + i * 32) * 64 + lphys * 8) * 2;
#pragma unroll
    for (int i = 0; i < 4; i++) sOffB[i] = ((lrow + i * 32) * 64 + lphys * 8) * 2;

    int wm = (wid & 1) * 32;
    int wn = (wid >> 1) * 32;
    int a_h = lane >> 4, a_r = lane & 15;
    int b_g = lane >> 3, b_sub = b_g >> 1, b_h = b_g & 1, b_r = lane & 7;

    int arow[2], axr[2];
#pragma unroll
    for (int mt = 0; mt < 2; mt++) {
        int r = wm + mt * 16 + a_r;
        arow[mt] = r * 64; axr[mt] = r & 7;
    }
    int brow[2], bxr[2];
#pragma unroll
    for (int p = 0; p < 2; p++) {
        int r = wn + p * 16 + b_sub * 8 + b_r;
        brow[p] = r * 64; bxr[p] = r & 7;
    }
    int gid = lane >> 2, tig = lane & 3;

    for (;;) {
        __syncthreads();   // previous tile fully done
        if (tid == 0) s_tile = atomicAdd(&g_tile_ctr, 1);
        __syncthreads();
        int t = s_tile;
        if (t >= g_ntiles) break;

        uint32_t enc = g_tiles[t];
        int e = enc >> 12;
        int mch = (enc >> 4) & 255;
        int l_base = (enc & 15) * TNB;
        int cnt = g_counts[e];

        if (tid < TMB) {
            int i = mch * TMB + tid;
            rowids[tid] = (i < cnt) ? g_rows[e][i] : -1;
        }
        __syncthreads();

        const __half* gA[2];
        const __half* gB[4];
        bool apred[2];
#pragma unroll
        for (int i = 0; i < 2; i++) {
            int row = lrow + i * 32;
            int g = rowids[row];
            apred[i] = (g >= 0);
            gA[i] = g_hid_h + (size_t)(apred[i] ? g : 0) * H_N + lcc * 8;
        }
#pragma unroll
        for (int i = 0; i < 4; i++) {
            int row = lrow + i * 32;
            gB[i] = g_W_h + ((size_t)e * L_N + l_base + row) * H_N + lcc * 8;
        }

        float acc[2][4][4];
#pragma unroll
        for (int mt = 0; mt < 2; mt++)
#pragma unroll
            for (int nt = 0; nt < 4; nt++)
#pragma unroll
                for (int j = 0; j < 4; j++) acc[mt][nt][j] = 0.f;

        // preload stages 0,1 (each stage = 2 k-blocks of 64)
#pragma unroll
        for (int p = 0; p < NSTAGE - 1; p++) {
            uint32_t b = stb[p];
            int koff = p * TK;
#pragma unroll
            for (int kb = 0; kb < 2; kb++) {
                int ko = koff + kb * 64;
#pragma unroll
                for (int i = 0; i < 2; i++)
                    cp16(b + kb * 8192 + sOffA[i], gA[i] + ko, apred[i]);
#pragma unroll
                for (int i = 0; i < 4; i++)
                    cp16(b + 16384 + kb * 16384 + sOffB[i], gB[i] + ko, true);
            }
            asm volatile("cp.async.commit_group;");
        }

        int cur = 0, nxt = NSTAGE - 1;
        for (int it = 0; it < NIT; it++) {
            asm volatile("cp.async.wait_group 1;");
            __syncthreads();

            int nc = it + NSTAGE - 1;
            if (nc < NIT) {
                uint32_t b = stb[nxt];
                int koff = nc * TK;
#pragma unroll
                for (int kb = 0; kb < 2; kb++) {
                    int ko = koff + kb * 64;
#pragma unroll
                    for (int i = 0; i < 2; i++)
                        cp16(b + kb * 8192 + sOffA[i], gA[i] + ko, apred[i]);
#pragma unroll
                    for (int i = 0; i < 4; i++)
                        cp16(b + 16384 + kb * 16384 + sOffB[i], gB[i] + ko, true);
                }
            }
            asm volatile("cp.async.commit_group;");

            uint32_t base = stb[cur];
            uint32_t af[2][2][4], bf[2][4][2];

            LOAD_FRAG(0, 0);
#pragma unroll
            for (int s4 = 0; s4 < 8; s4++) {
                int cb = s4 & 1, nb = cb ^ 1;
                if (s4 < 7) LOAD_FRAG(nb, s4 + 1);
#pragma unroll
                for (int mt = 0; mt < 2; mt++)
#pragma unroll
                    for (int nt = 0; nt < 4; nt++)
                        MMAF16(acc[mt][nt], af[cb][mt], bf[cb][nt][0], bf[cb][nt][1]);
            }
            cur = (cur + 1 == NSTAGE) ? 0 : cur + 1;
            nxt = (nxt + 1 == NSTAGE) ? 0 : nxt + 1;
        }

        // ---- epilogue ----
#pragma unroll
        for (int mt = 0; mt < 2; mt++) {
            int r0 = wm + mt * 16 + gid;
            int r1 = r0 + 8;
            int g0 = rowids[r0];
            int g1 = rowids[r1];
#pragma unroll
            for (int nt = 0; nt < 4; nt++) {
                int col = l_base + wn + nt * 8 + tig * 2;
                if (g0 >= 0)
                    *(float2*)(out + (size_t)g0 * L_N + col) =
                        make_float2(acc[mt][nt][0], acc[mt][nt][1]);
                if (g1 >= 0)
                    *(float2*)(out + (size_t)g1 * L_N + col) =
                        make_float2(acc[mt][nt][2], acc[mt][nt][3]);
            }
        }
    }
}

// ---------------- launch ----------------
extern "C" void kernel_launch(void* const* d_in, const int* in_sizes, int n_in,
                              void* d_out, int out_size) {
    const float* hidden = (const float*)d_in[0];
    const float* envs   = (const float*)d_in[1];
    const int*   idx32  = (const int*)d_in[2];
    const float* gumbel = (const float*)d_in[3];
    const float* W      = (const float*)d_in[4];
    float* out = (float*)d_out;

    cudaFuncSetAttribute(gemm_kernel,
                         cudaFuncAttributeMaxDynamicSharedMemorySize, SMEM_DYN);

    convert_kernel<<<CVT_GRID, 256>>>(W, hidden);      // + init (block 0)
    select_kernel<<<B_N / 256, 256>>>(envs, idx32, gumbel);  // + tile build
    stats_kernel<<<ST_GRID, ST_BLK>>>();               // penalty stats from fp16 W

    gemm_kernel<<<GRID_GEMM, 256, SMEM_DYN>>>(out);

    if (out_size > B_N * L_N)
        finalize_kernel<<<1, 32>>>(out + (size_t)B_N * L_N);
}